// round 4
// baseline (speedup 1.0000x reference)
#include <cuda_runtime.h>
#include <stdint.h>

// Sampling_26972394619348
// w = z_mean[:,None,:] + exp(0.5*z_log_var)[:,None,:] * epsilon   [B,100,3]
// labels_ext = repeat(labels, 100) emitted as float32 values.
//
// Inputs: d_in[0] z_mean f32[B,3], d_in[1] z_log_var f32[B,3],
//         d_in[2] labels i32[B], d_in[3] epsilon f32[B,100,3]
// Output: w.flatten() [B*300 f32] then labels_ext [B*100 f32].
//
// Fully coalesced layout: thread i handles float4 i of the w stream
// (75 float4s per batch row; 300 % 4 == 0 so no row crossing).
// Component phase of float4 j within a row: ph = (4j) mod 3 = j mod 3:
//   ph=0 -> (x y z x), ph=1 -> (y z x y), ph=2 -> (z x y z)
// Tail range of the grid writes the label region (one float4 = 4 samples).

__device__ __forceinline__ float pick3(unsigned c, float a0, float a1, float a2) {
    return c == 0 ? a0 : (c == 1 ? a1 : a2);
}

__global__ void __launch_bounds__(256)
sampling_kernel(const float* __restrict__ zm,
                const float* __restrict__ lv,
                const int*   __restrict__ labels,
                const float4* __restrict__ eps4,
                float4* __restrict__ w4,
                float4* __restrict__ lab4,
                unsigned nw4,    // B*75
                unsigned nl4)    // B*25
{
    unsigned i = blockIdx.x * blockDim.x + threadIdx.x;

    if (i < nw4) {
        unsigned b  = i / 75u;
        unsigned j  = i - b * 75u;
        unsigned ph = j % 3u;

        float zx = __ldg(&zm[3u*b + 0]);
        float zy = __ldg(&zm[3u*b + 1]);
        float zz = __ldg(&zm[3u*b + 2]);
        float sx = __expf(0.5f * __ldg(&lv[3u*b + 0]));
        float sy = __expf(0.5f * __ldg(&lv[3u*b + 1]));
        float sz = __expf(0.5f * __ldg(&lv[3u*b + 2]));

        // component indices for the 4 lanes of this float4
        unsigned c0 = ph;                        // (ph + 0) % 3
        unsigned c1 = (ph == 2u) ? 0u : ph + 1u; // (ph + 1) % 3
        unsigned c2 = (ph == 0u) ? 2u : ph - 1u; // (ph + 2) % 3

        float m0 = pick3(c0, zx, zy, zz), s0 = pick3(c0, sx, sy, sz);
        float m1 = pick3(c1, zx, zy, zz), s1 = pick3(c1, sx, sy, sz);
        float m2 = pick3(c2, zx, zy, zz), s2 = pick3(c2, sx, sy, sz);

        float4 e = eps4[i];
        float4 o;
        o.x = fmaf(s0, e.x, m0);
        o.y = fmaf(s1, e.y, m1);
        o.z = fmaf(s2, e.z, m2);
        o.w = fmaf(s0, e.w, m0);   // 4th element wraps back to c0
        w4[i] = o;
    } else {
        unsigned q = i - nw4;
        if (q < nl4) {
            unsigned b = q / 25u;            // 25 float4s (100 samples) per row
            float lf = (float)__ldg(&labels[b]);
            lab4[q] = make_float4(lf, lf, lf, lf);
        }
    }
}

extern "C" void kernel_launch(void* const* d_in, const int* in_sizes, int n_in,
                              void* d_out, int out_size)
{
    const float* zm     = (const float*)d_in[0];
    const float* lv     = (const float*)d_in[1];
    const int*   labels = (const int*)d_in[2];
    const float4* eps4  = (const float4*)d_in[3];

    const unsigned B   = (unsigned)in_sizes[2];   // labels element count
    const unsigned nw4 = B * 75u;                 // float4s in w region
    const unsigned nl4 = B * 25u;                 // float4s in label region

    float4* w4   = (float4*)d_out;
    float4* lab4 = (float4*)((float*)d_out + (size_t)B * 300u);

    const unsigned total = nw4 + nl4;
    const int block = 256;
    const unsigned grid = (total + block - 1) / block;

    sampling_kernel<<<grid, block>>>(zm, lv, labels, eps4, w4, lab4, nw4, nl4);
}

// round 5
// speedup vs baseline: 1.3331x; 1.3331x over previous
#include <cuda_runtime.h>
#include <stdint.h>

// Sampling_26972394619348
// w = z_mean[:,None,:] + exp(0.5*z_log_var)[:,None,:] * epsilon   [B,100,3]
// labels_ext = repeat(labels, 100) emitted as float32 values.
//
// Inputs: d_in[0] z_mean f32[B,3], d_in[1] z_log_var f32[B,3],
//         d_in[2] labels i32[B], d_in[3] epsilon f32[B,100,3]
// Output: w.flatten() [B*300 f32] then labels_ext [B*100 f32].
//
// w region: each block owns TILE=768 consecutive float4s (256 thr x 3,
// block-strided by 256 -> every global access fully coalesced).
// Row stats (mean, std) for the <=12 rows a block touches are staged in
// shared memory once, so the streaming loop does no global scalar loads
// and no expf. Phase of float4 idx is idx%3; with 768%3==0, 256%3==1 it
// reduces to (t+k)%3. Component of the 4 lanes: (ph, ph+1, ph+2, ph) mod 3.

#define BLOCK   256
#define VEC     3
#define TILE    (BLOCK * VEC)   // 768 float4s per block
#define NROWS   12              // max rows a 768-float4 tile can span

__global__ void __launch_bounds__(BLOCK)
sampling_kernel(const float* __restrict__ zm,
                const float* __restrict__ lv,
                const int*   __restrict__ labels,
                const float4* __restrict__ eps4,
                float4* __restrict__ w4,
                float4* __restrict__ lab4,
                unsigned wblocks,   // blocks covering the w region
                unsigned B,
                unsigned nl4)       // B*25 label float4s
{
    __shared__ float sm_m[NROWS * 3];
    __shared__ float sm_s[NROWS * 3];

    const unsigned t = threadIdx.x;

    if (blockIdx.x < wblocks) {
        const unsigned base    = blockIdx.x * TILE;     // first float4 index
        const unsigned rowbase = base / 75u;

        // Stage row stats: one thread per row.
        if (t < NROWS) {
            unsigned row = rowbase + t;
            if (row < B) {
                sm_m[t*3 + 0] = __ldg(&zm[3u*row + 0]);
                sm_m[t*3 + 1] = __ldg(&zm[3u*row + 1]);
                sm_m[t*3 + 2] = __ldg(&zm[3u*row + 2]);
                sm_s[t*3 + 0] = __expf(0.5f * __ldg(&lv[3u*row + 0]));
                sm_s[t*3 + 1] = __expf(0.5f * __ldg(&lv[3u*row + 1]));
                sm_s[t*3 + 2] = __expf(0.5f * __ldg(&lv[3u*row + 2]));
            }
        }
        __syncthreads();

        #pragma unroll
        for (int k = 0; k < VEC; k++) {
            const unsigned idx = base + (unsigned)k * BLOCK + t;
            const unsigned lr  = idx / 75u - rowbase;       // local row
            const unsigned ph  = (t + (unsigned)k) % 3u;    // idx % 3
            const unsigned c1  = (ph == 2u) ? 0u : ph + 1u;
            const unsigned c2  = (ph == 0u) ? 2u : ph - 1u;

            const float m0 = sm_m[lr*3 + ph], s0 = sm_s[lr*3 + ph];
            const float m1 = sm_m[lr*3 + c1], s1 = sm_s[lr*3 + c1];
            const float m2 = sm_m[lr*3 + c2], s2 = sm_s[lr*3 + c2];

            const float4 e = __ldcs(&eps4[idx]);
            float4 o;
            o.x = fmaf(s0, e.x, m0);
            o.y = fmaf(s1, e.y, m1);
            o.z = fmaf(s2, e.z, m2);
            o.w = fmaf(s0, e.w, m0);
            __stcs(&w4[idx], o);
        }
    } else {
        // Label region: one float4 (4 samples) per thread, coalesced.
        const unsigned q = (blockIdx.x - wblocks) * BLOCK + t;
        if (q < nl4) {
            const unsigned b = q / 25u;   // 25 float4s per batch row
            const float lf = (float)__ldg(&labels[b]);
            __stcs(&lab4[q], make_float4(lf, lf, lf, lf));
        }
    }
}

extern "C" void kernel_launch(void* const* d_in, const int* in_sizes, int n_in,
                              void* d_out, int out_size)
{
    const float*  zm     = (const float*)d_in[0];
    const float*  lv     = (const float*)d_in[1];
    const int*    labels = (const int*)d_in[2];
    const float4* eps4   = (const float4*)d_in[3];

    const unsigned B   = (unsigned)in_sizes[2];  // labels element count
    const unsigned nw4 = B * 75u;                // float4s in w region
    const unsigned nl4 = B * 25u;                // float4s in label region

    float4* w4   = (float4*)d_out;
    float4* lab4 = (float4*)((float*)d_out + (size_t)B * 300u);

    const unsigned wblocks = (nw4 + TILE - 1) / TILE;    // 25600 for B=262144
    const unsigned lblocks = (nl4 + BLOCK - 1) / BLOCK;  // 25600
    const unsigned grid    = wblocks + lblocks;

    sampling_kernel<<<grid, BLOCK>>>(zm, lv, labels, eps4, w4, lab4,
                                     wblocks, B, nl4);
}

// round 6
// speedup vs baseline: 1.3599x; 1.0200x over previous
#include <cuda_runtime.h>
#include <stdint.h>

// Sampling_26972394619348
// w = z_mean[:,None,:] + exp(0.5*z_log_var)[:,None,:] * epsilon   [B,100,3]
// labels_ext = repeat(labels, 100) emitted as float32 values.
//
// Inputs: d_in[0] z_mean f32[B,3], d_in[1] z_log_var f32[B,3],
//         d_in[2] labels i32[B], d_in[3] epsilon f32[B,100,3]
// Output: w.flatten() [B*300 f32] then labels_ext [B*100 f32].
//
// w region: each block owns TILE=1536 consecutive float4s (256 thr x 6,
// block-strided by 256 -> fully coalesced). Loads are front-batched
// (6 outstanding LDG.128 per thread) to maximize MLP before compute/store.
// Row stats for the <=22 rows a block touches are staged in smem once.
// Phase: TILE%3==0, 256%3==1 -> ph(idx)=(t+k)%3.

#define BLOCK   256
#define VEC     6
#define TILE    (BLOCK * VEC)   // 1536 float4s per block
#define NROWS   22              // max rows a 1536-float4 tile can span
#define LVEC    4               // float4s per thread in the label region

__global__ void __launch_bounds__(BLOCK)
sampling_kernel(const float* __restrict__ zm,
                const float* __restrict__ lv,
                const int*   __restrict__ labels,
                const float4* __restrict__ eps4,
                float4* __restrict__ w4,
                float4* __restrict__ lab4,
                unsigned wblocks,   // blocks covering the w region
                unsigned B,
                unsigned nl4)       // B*25 label float4s
{
    __shared__ float sm_m[NROWS * 3];
    __shared__ float sm_s[NROWS * 3];

    const unsigned t = threadIdx.x;

    if (blockIdx.x < wblocks) {
        const unsigned base    = blockIdx.x * TILE;     // first float4 index
        const unsigned rowbase = base / 75u;

        // Stage row stats: one thread per row.
        if (t < NROWS) {
            unsigned row = rowbase + t;
            if (row < B) {
                sm_m[t*3 + 0] = __ldg(&zm[3u*row + 0]);
                sm_m[t*3 + 1] = __ldg(&zm[3u*row + 1]);
                sm_m[t*3 + 2] = __ldg(&zm[3u*row + 2]);
                sm_s[t*3 + 0] = __expf(0.5f * __ldg(&lv[3u*row + 0]));
                sm_s[t*3 + 1] = __expf(0.5f * __ldg(&lv[3u*row + 1]));
                sm_s[t*3 + 2] = __expf(0.5f * __ldg(&lv[3u*row + 2]));
            }
        }
        __syncthreads();

        // Front-batched loads: all VEC loads issued before any dependent use.
        float4 e[VEC];
        #pragma unroll
        for (int k = 0; k < VEC; k++)
            e[k] = __ldcs(&eps4[base + (unsigned)k * BLOCK + t]);

        #pragma unroll
        for (int k = 0; k < VEC; k++) {
            const unsigned idx = base + (unsigned)k * BLOCK + t;
            const unsigned lr  = idx / 75u - rowbase;       // local row
            const unsigned ph  = (t + (unsigned)k) % 3u;    // idx % 3
            const unsigned c1  = (ph == 2u) ? 0u : ph + 1u;
            const unsigned c2  = (ph == 0u) ? 2u : ph - 1u;

            const float m0 = sm_m[lr*3 + ph], s0 = sm_s[lr*3 + ph];
            const float m1 = sm_m[lr*3 + c1], s1 = sm_s[lr*3 + c1];
            const float m2 = sm_m[lr*3 + c2], s2 = sm_s[lr*3 + c2];

            float4 o;
            o.x = fmaf(s0, e[k].x, m0);
            o.y = fmaf(s1, e[k].y, m1);
            o.z = fmaf(s2, e[k].z, m2);
            o.w = fmaf(s0, e[k].w, m0);
            __stcs(&w4[idx], o);
        }
    } else {
        // Label region: LVEC coalesced float4 stores per thread.
        const unsigned q0 = (blockIdx.x - wblocks) * (BLOCK * LVEC) + t;
        #pragma unroll
        for (int k = 0; k < LVEC; k++) {
            const unsigned q = q0 + (unsigned)k * BLOCK;
            if (q < nl4) {
                const unsigned b = q / 25u;   // 25 float4s per batch row
                const float lf = (float)__ldg(&labels[b]);
                __stcs(&lab4[q], make_float4(lf, lf, lf, lf));
            }
        }
    }
}

extern "C" void kernel_launch(void* const* d_in, const int* in_sizes, int n_in,
                              void* d_out, int out_size)
{
    const float*  zm     = (const float*)d_in[0];
    const float*  lv     = (const float*)d_in[1];
    const int*    labels = (const int*)d_in[2];
    const float4* eps4   = (const float4*)d_in[3];

    const unsigned B   = (unsigned)in_sizes[2];  // labels element count
    const unsigned nw4 = B * 75u;                // float4s in w region
    const unsigned nl4 = B * 25u;                // float4s in label region

    float4* w4   = (float4*)d_out;
    float4* lab4 = (float4*)((float*)d_out + (size_t)B * 300u);

    const unsigned wblocks = (nw4 + TILE - 1) / TILE;            // 12800
    const unsigned lblocks = (nl4 + BLOCK*LVEC - 1) / (BLOCK*LVEC); // 6400
    const unsigned grid    = wblocks + lblocks;

    sampling_kernel<<<grid, BLOCK>>>(zm, lv, labels, eps4, w4, lab4,
                                     wblocks, B, nl4);
}